// round 1
// baseline (speedup 1.0000x reference)
#include <cuda_runtime.h>
#include <math.h>

#define NB 512   // batch
#define NF 512   // features
#define NS 255   // splits
#define NN 511   // nodes
#define NC 21    // candidates

// ---------------- scratch (no allocations allowed) ----------------
__device__ float g_qsplit[NB * NS];
__device__ float g_qnode [NB * NN];   // [b][n]  (for final clip, coalesced with out)
__device__ float g_qnodeT[NN * NB];   // [n][b]  (for coalesced batch reduction)
__device__ float g_ga    [NN * NC];
__device__ float g_anode [NN];

// ---------------- kernel 1: q_split = x @ W + b ----------------
// 64x64 tile, 256 threads, 4x4 per-thread micro-tile, K panel = 16
__global__ void gemm_kernel(const float* __restrict__ x,
                            const float* __restrict__ W,
                            const float* __restrict__ bias)
{
    __shared__ float As[64][17];
    __shared__ float Bs[16][65];

    int tid = threadIdx.x;          // 0..255
    int tc = tid & 15;              // 0..15
    int tr = tid >> 4;              // 0..15
    int rowBase = blockIdx.y * 64;
    int colBase = blockIdx.x * 64;

    float acc[4][4];
#pragma unroll
    for (int i = 0; i < 4; i++)
#pragma unroll
        for (int j = 0; j < 4; j++) acc[i][j] = 0.0f;

    for (int k0 = 0; k0 < NF; k0 += 16) {
#pragma unroll
        for (int i = 0; i < 4; i++) {
            int e = tid + i * 256;
            int r = e >> 4, c = e & 15;
            As[r][c] = x[(rowBase + r) * NF + k0 + c];
        }
#pragma unroll
        for (int i = 0; i < 4; i++) {
            int e = tid + i * 256;
            int r = e >> 6, c = e & 63;
            int gc = colBase + c;
            Bs[r][c] = (gc < NS) ? W[(k0 + r) * NS + gc] : 0.0f;
        }
        __syncthreads();

#pragma unroll
        for (int kk = 0; kk < 16; kk++) {
            float a[4], b[4];
#pragma unroll
            for (int i = 0; i < 4; i++) a[i] = As[tr * 4 + i][kk];
#pragma unroll
            for (int j = 0; j < 4; j++) b[j] = Bs[kk][tc * 4 + j];
#pragma unroll
            for (int i = 0; i < 4; i++)
#pragma unroll
                for (int j = 0; j < 4; j++) acc[i][j] += a[i] * b[j];
        }
        __syncthreads();
    }

#pragma unroll
    for (int i = 0; i < 4; i++) {
        int row = rowBase + tr * 4 + i;
#pragma unroll
        for (int j = 0; j < 4; j++) {
            int col = colBase + tc * 4 + j;
            if (col < NS)
                g_qsplit[row * NS + col] = acc[i][j] + bias[col];
        }
    }
}

// ---------------- kernel 2: q_node via ancestor walk ----------------
// q_node[b,n] = min(1, min over ancestors: (left child ? -1 : +1) * q_split[b, parent])
__global__ void qnode_kernel()
{
    __shared__ float qs[NS];
    int b = blockIdx.x;
    int tid = threadIdx.x;   // 512 threads
    if (tid < NS) qs[tid] = g_qsplit[b * NS + tid];
    __syncthreads();
    if (tid < NN) {
        float m = 1.0f;
        int a = tid;
        while (a > 0) {
            int p = (a - 1) >> 1;
            float v = qs[p];
            if (a == 2 * p + 1) v = -v;   // left child -> sign -1
            m = fminf(m, v);
            a = p;
        }
        g_qnode [b * NN + tid] = m;
        g_qnodeT[tid * NB + b] = m;
    }
}

// ---------------- kernel 3: g_a[n,c] reduction over batch ----------------
__global__ void ga_kernel()
{
    __shared__ float sred[NC][256];
    int n = blockIdx.x;
    int tid = threadIdx.x;   // 256 threads

    float acc[NC];
#pragma unroll
    for (int c = 0; c < NC; c++) acc[c] = 0.0f;

    for (int b = tid; b < NB; b += 256) {
        float qh = g_qnodeT[n * NB + b] + 0.5f;
#pragma unroll
        for (int c = 0; c < NC; c++) {
            float a = (float)c / 20.0f;
            float d = a - qh;
            if (a <= qh) acc[c] += d * d;
        }
    }
#pragma unroll
    for (int c = 0; c < NC; c++) sred[c][tid] = acc[c];
    __syncthreads();

    for (int s = 128; s >= 1; s >>= 1) {
        if (tid < s) {
#pragma unroll
            for (int c = 0; c < NC; c++) sred[c][tid] += sred[c][tid + s];
        }
        __syncthreads();
    }
    if (tid < NC) {
        float a = (float)tid / 20.0f;
        g_ga[n * NC + tid] = 0.5f * a * a + 0.5f * sred[tid][0];
    }
}

// ---------------- kernel 4: the scan, single block ----------------
// n2g row n == (1-k[n])*e_n + k[n]*e_parent(n). State is just k[].
__device__ __forceinline__ float softmin_group(int g, const int* sK)
{
    float kg = (float)sK[g];
    int c1 = 2 * g + 1, c2 = 2 * g + 2;
    float k1 = (c1 < NN) ? (float)sK[c1] : 0.0f;
    float k2 = (c2 < NN) ? (float)sK[c2] : 0.0f;
    const float* r0 = &g_ga[g * NC];
    const float* r1 = (c1 < NN) ? &g_ga[c1 * NC] : r0;
    const float* r2 = (c2 < NN) ? &g_ga[c2 * NC] : r0;

    float s[NC];
    float m = -3.0e38f;
#pragma unroll
    for (int c = 0; c < NC; c++) {
        float v = (1.0f - kg) * r0[c] + k1 * r1[c] + k2 * r2[c];
        s[c] = -100.0f * v;
        m = fmaxf(m, s[c]);
    }
    float sum = 0.0f, asum = 0.0f;
#pragma unroll
    for (int c = 0; c < NC; c++) {
        float e = expf(s[c] - m);
        sum += e;
        asum += ((float)c / 20.0f) * e;
    }
    return asum / sum;
}

__global__ void scan_kernel()
{
    __shared__ float sAgrp[NN];
    __shared__ float sAnode[NN];
    __shared__ int   sK[NN];
    __shared__ float sWv[16];
    __shared__ int   sWi[16];
    __shared__ int   sT;

    int tid = threadIdx.x;   // 512
    if (tid < NN) sK[tid] = 0;
    __syncthreads();
    if (tid < NN) sAgrp[tid] = softmin_group(tid, sK);

    int iter = 0;
    while (true) {
        __syncthreads();
        // a_node[n] = (1-k)*a_grp[n] + k*a_grp[parent(n)]
        if (tid < NN) {
            float kf = (float)sK[tid];
            float a = (1.0f - kf) * sAgrp[tid];
            if (tid > 0) a += kf * sAgrp[(tid - 1) >> 1];
            sAnode[tid] = a;
        }
        __syncthreads();

        // viol + first-index argmax
        float v = -3.0e38f;
        int idx = NN;
        if (tid < NN) {
            v = sAnode[tid] - ((tid > 0) ? sAnode[(tid - 1) >> 1] : 1.0f);
            idx = tid;
        }
#pragma unroll
        for (int o = 16; o > 0; o >>= 1) {
            float ov = __shfl_down_sync(0xffffffffu, v, o);
            int   oi = __shfl_down_sync(0xffffffffu, idx, o);
            if (ov > v || (ov == v && oi < idx)) { v = ov; idx = oi; }
        }
        if ((tid & 31) == 0) { sWv[tid >> 5] = v; sWi[tid >> 5] = idx; }
        __syncthreads();
        if (tid == 0) {
            float bv = sWv[0]; int bi = sWi[0];
            for (int w = 1; w < 16; w++) {
                if (sWv[w] > bv || (sWv[w] == bv && sWi[w] < bi)) { bv = sWv[w]; bi = sWi[w]; }
            }
            // merge only if NO violation (> 1e-8) anywhere AND argmax isn't root
            sT = (bv <= 1e-8f && bi > 0) ? bi : -1;
        }
        __syncthreads();
        int t = sT;
        if (t < 0) break;        // no-op iteration -> all further iterations identical
        if (iter >= NN) break;   // body call 512's update is discarded by the scan
        if (tid == 0) sK[t] += 1;
        __syncthreads();
        if (tid == 0)      sAgrp[(t - 1) >> 1] = softmin_group((t - 1) >> 1, sK);
        else if (tid == 1) sAgrp[t]            = softmin_group(t, sK);
        iter++;
    }
    __syncthreads();
    if (tid < NN) g_anode[tid] = sAnode[tid];
}

// ---------------- kernel 5: trajectory = clip(q_node, 0, a_node) ----------------
__global__ void traj_kernel(float* __restrict__ out)
{
    int i = blockIdx.x * blockDim.x + threadIdx.x;
    if (i < NB * NN) {
        int n = i % NN;
        out[i] = fminf(fmaxf(g_qnode[i], 0.0f), g_anode[n]);
    }
}

// ---------------- launch ----------------
extern "C" void kernel_launch(void* const* d_in, const int* in_sizes, int n_in,
                              void* d_out, int out_size)
{
    const float* x = (const float*)d_in[0];
    const float* W = (const float*)d_in[1];
    const float* b = (const float*)d_in[2];
    // d_in[3] = max_depth (fixed at 8; shapes hardcoded)

    gemm_kernel <<<dim3((NS + 63) / 64, NB / 64), 256>>> (x, W, b);
    qnode_kernel<<<NB, 512>>>();
    ga_kernel   <<<NN, 256>>>();
    scan_kernel <<<1, 512>>>();
    traj_kernel <<<(NB * NN + 255) / 256, 256>>>((float*)d_out);
}

// round 2
// speedup vs baseline: 1.7198x; 1.7198x over previous
#include <cuda_runtime.h>
#include <math.h>

#define NB 512   // batch
#define NF 512   // features
#define NS 255   // splits
#define NN 511   // nodes
#define NC 21    // candidates

#define QSCALE 268435456.0   // 2^28 (double, for exact fixed-point convert)
#define QINV   3.7252902984619140625e-09f  // 2^-28

// ---------------- scratch (no allocations allowed) ----------------
__device__ unsigned long long g_qsplitI[NS * NB]; // [s][b] fixed-point accum (zeroed at end of traj)
__device__ float g_qnodeT[NN * NB];               // [n][b]
__device__ float g_ga    [NN * NC];
__device__ float g_anode [NN];

// ================= kernel 1: split-K GEMM, transposed output =================
// qsplitT[s][b] = sum_f W[f][s] * x[b][f]   (bias added by consumers)
// grid: (ksplit=8, bTile=8, sTile=4), block 256, each block 64x64x64 panel.
// Deterministic: fixed-point int64 atomic accumulation.
__global__ __launch_bounds__(256, 2)
void gemm_kernel(const float* __restrict__ x, const float* __restrict__ W)
{
    __shared__ float As[64][68];   // [f][s], row stride 272B (16B aligned)
    __shared__ float Bs[64][68];   // [f][b]

    int tid   = threadIdx.x;
    int k0    = blockIdx.x * 64;
    int bBase = blockIdx.y * 64;
    int sBase = blockIdx.z * 64;

    {
        int s = tid & 63, f0 = tid >> 6;       // 4 rows per pass
        int gs = sBase + s;
#pragma unroll
        for (int i = 0; i < 16; i++) {
            int f = f0 + i * 4;
            As[f][s] = (gs < NS) ? W[(k0 + f) * NS + gs] : 0.0f;
        }
        int fb = tid & 63, b0 = tid >> 6;
#pragma unroll
        for (int i = 0; i < 16; i++) {
            int b = b0 + i * 4;
            Bs[fb][b] = x[(bBase + b) * NF + k0 + fb];
        }
    }
    __syncthreads();

    int tr = tid >> 4;   // s quad
    int tc = tid & 15;   // b quad
    float acc[4][4];
#pragma unroll
    for (int i = 0; i < 4; i++)
#pragma unroll
        for (int j = 0; j < 4; j++) acc[i][j] = 0.0f;

#pragma unroll
    for (int f = 0; f < 64; f++) {
        float4 a4 = *(const float4*)&As[f][tr * 4];
        float4 b4 = *(const float4*)&Bs[f][tc * 4];
        float av[4] = {a4.x, a4.y, a4.z, a4.w};
        float bv[4] = {b4.x, b4.y, b4.z, b4.w};
#pragma unroll
        for (int i = 0; i < 4; i++)
#pragma unroll
            for (int j = 0; j < 4; j++) acc[i][j] += av[i] * bv[j];
    }

#pragma unroll
    for (int i = 0; i < 4; i++) {
        int s = sBase + tr * 4 + i;
        if (s < NS) {
#pragma unroll
            for (int j = 0; j < 4; j++) {
                int b = bBase + tc * 4 + j;
                long long q = __double2ll_rn((double)acc[i][j] * QSCALE);
                atomicAdd(&g_qsplitI[s * NB + b], (unsigned long long)q);
            }
        }
    }
}

// ================= kernel 2: q_node (ancestor walk) + g_a reduction =================
// one block per node n; 256 threads, 2 batch elements each; coalesced over b.
__global__ __launch_bounds__(256)
void ga_kernel(const float* __restrict__ bias)
{
    int n   = blockIdx.x;
    int tid = threadIdx.x;

    float accs[NC];
#pragma unroll
    for (int c = 0; c < NC; c++) accs[c] = 0.0f;

#pragma unroll
    for (int rep = 0; rep < 2; rep++) {
        int b = tid + rep * 256;
        float m = 1.0f;
        int a = n;
        while (a > 0) {
            int p = (a - 1) >> 1;
            long long qv = (long long)g_qsplitI[p * NB + b];
            float q = (float)qv * QINV + bias[p];
            m = fminf(m, (a == 2 * p + 1) ? -q : q);
            a = p;
        }
        g_qnodeT[n * NB + b] = m;
        float qh = m + 0.5f;
#pragma unroll
        for (int c = 0; c < NC; c++) {
            float ac = (float)c * (1.0f / 20.0f);
            float d = ac - qh;
            if (ac <= qh) accs[c] += d * d;
        }
    }

    // warp reduce 21 accumulators
#pragma unroll
    for (int c = 0; c < NC; c++)
#pragma unroll
        for (int o = 16; o > 0; o >>= 1)
            accs[c] += __shfl_down_sync(0xffffffffu, accs[c], o);

    __shared__ float sW[8][NC];
    int w = tid >> 5, l = tid & 31;
    if (l == 0) {
#pragma unroll
        for (int c = 0; c < NC; c++) sW[w][c] = accs[c];
    }
    __syncthreads();
    if (tid < NC) {
        float s = 0.0f;
#pragma unroll
        for (int ww = 0; ww < 8; ww++) s += sW[ww][tid];
        float ac = (float)tid * (1.0f / 20.0f);
        g_ga[n * NC + tid] = 0.5f * ac * ac + 0.5f * s;
    }
}

// ================= kernel 3: the scan =================
// n2g row n == (1-k[n])*e_n + k[n]*e_parent(n); state is integer k[].
__device__ __forceinline__ void softmin_warp(int g, const float* sGa,
                                             const int* sK, float* sAgrp)
{
    int lane = threadIdx.x & 31;
    float kg = (float)sK[g];
    int c1 = 2 * g + 1, c2 = 2 * g + 2;
    float s;
    if (lane < NC) {
        float v = (1.0f - kg) * sGa[g * NC + lane];
        if (c1 < NN) v += (float)sK[c1] * sGa[c1 * NC + lane];
        if (c2 < NN) v += (float)sK[c2] * sGa[c2 * NC + lane];
        s = -100.0f * v;
    } else {
        s = -3.0e38f;
    }
    float m = s;
#pragma unroll
    for (int o = 16; o > 0; o >>= 1) m = fmaxf(m, __shfl_xor_sync(0xffffffffu, m, o));
    float e  = (lane < NC) ? __expf(s - m) : 0.0f;
    float ae = e * ((float)lane * (1.0f / 20.0f));
#pragma unroll
    for (int o = 16; o > 0; o >>= 1) {
        e  += __shfl_xor_sync(0xffffffffu, e, o);
        ae += __shfl_xor_sync(0xffffffffu, ae, o);
    }
    if (lane == 0) sAgrp[g] = ae / e;
}

__global__ __launch_bounds__(512)
void scan_kernel()
{
    __shared__ float sGa[NN * NC];   // 42924 B
    __shared__ float sAgrp[NN];
    __shared__ int   sK[NN];
    __shared__ float sWv[16];
    __shared__ int   sWi[16];
    __shared__ int   sT;

    int tid = threadIdx.x;

    for (int i = tid; i < NN * NC; i += 512) sGa[i] = g_ga[i];
    if (tid < NN) sK[tid] = 0;
    __syncthreads();

    // initial a_grp: all k==0 -> softmin of own row only
    if (tid < NN) {
        const float* r = &sGa[tid * NC];
        float m = -3.0e38f;
#pragma unroll
        for (int c = 0; c < NC; c++) m = fmaxf(m, -100.0f * r[c]);
        float sum = 0.0f, asum = 0.0f;
#pragma unroll
        for (int c = 0; c < NC; c++) {
            float e = __expf(-100.0f * r[c] - m);
            sum += e;
            asum += (float)c * (1.0f / 20.0f) * e;
        }
        sAgrp[tid] = asum / sum;
    }

    int applied = 0;
    for (;;) {
        __syncthreads();   // sAgrp / sK stable

        // per-thread: a_node(n), a_node(parent(n)), violation — no extra barrier
        float v; int idx;
        if (tid < NN) {
            float an, apar;
            float agn = sAgrp[tid];
            if (tid == 0) {
                an = agn;            // k[0] is always 0 (merges require t>0)
                apar = 1.0f;
            } else {
                int p = (tid - 1) >> 1;
                float k = (float)sK[tid];
                an = (1.0f - k) * agn + k * sAgrp[p];
                float kp = (float)sK[p];
                float ap = sAgrp[p];
                apar = (p > 0) ? (1.0f - kp) * ap + kp * sAgrp[(p - 1) >> 1] : ap;
            }
            v = an - apar; idx = tid;
        } else { v = -3.0e38f; idx = NN; }

#pragma unroll
        for (int o = 16; o > 0; o >>= 1) {
            float ov = __shfl_down_sync(0xffffffffu, v, o);
            int   oi = __shfl_down_sync(0xffffffffu, idx, o);
            if (ov > v || (ov == v && oi < idx)) { v = ov; idx = oi; }
        }
        if ((tid & 31) == 0) { sWv[tid >> 5] = v; sWi[tid >> 5] = idx; }
        __syncthreads();

        if (tid < 32) {
            float bv = (tid < 16) ? sWv[tid] : -3.0e38f;
            int   bi = (tid < 16) ? sWi[tid] : NN;
#pragma unroll
            for (int o = 8; o > 0; o >>= 1) {
                float ov = __shfl_down_sync(0xffffffffu, bv, o);
                int   oi = __shfl_down_sync(0xffffffffu, bi, o);
                if (ov > bv || (ov == bv && oi < bi)) { bv = ov; bi = oi; }
            }
            if (tid == 0) {
                int t = (bv <= 1e-8f && bi > 0) ? bi : -1;
                sT = t;
                if (t >= 0 && applied < NN) sK[t] += 1;  // fold update before the barrier
            }
        }
        __syncthreads();

        int t = sT;
        if (t < 0 || applied >= NN) break;  // fixed point, or 512th body's merge is discarded
        applied++;

        int w = tid >> 5;
        if (w == 0)      softmin_warp((t - 1) >> 1, sGa, sK, sAgrp);
        else if (w == 1) softmin_warp(t,            sGa, sK, sAgrp);
    }

    // recompute final a_node from the state used in the last phase
    if (tid < NN) {
        float an;
        if (tid == 0) an = sAgrp[0];
        else {
            float k = (float)sK[tid];
            an = (1.0f - k) * sAgrp[tid] + k * sAgrp[(tid - 1) >> 1];
        }
        g_anode[tid] = an;
    }
}

// ================= kernel 4: trajectory + re-zero the GEMM accumulator =================
__global__ __launch_bounds__(512)
void traj_kernel(float* __restrict__ out)
{
    int b   = blockIdx.x;
    int tid = threadIdx.x;
    if (tid < NN) {
        float q = g_qnodeT[tid * NB + b];
        out[b * NN + tid] = fminf(fmaxf(q, 0.0f), g_anode[tid]);
    }
    // re-zero fixed-point accumulator for the next launch (rows 0..254)
    if (b < NS) g_qsplitI[b * NB + tid] = 0ULL;
}

// ---------------- launch ----------------
extern "C" void kernel_launch(void* const* d_in, const int* in_sizes, int n_in,
                              void* d_out, int out_size)
{
    const float* x = (const float*)d_in[0];
    const float* W = (const float*)d_in[1];
    const float* b = (const float*)d_in[2];
    // d_in[3] = max_depth (fixed at 8; shapes hardcoded)

    gemm_kernel<<<dim3(8, 8, 4), 256>>>(x, W);
    ga_kernel  <<<NN, 256>>>(b);
    scan_kernel<<<1, 512>>>();
    traj_kernel<<<NB, 512>>>((float*)d_out);
}